// round 1
// baseline (speedup 1.0000x reference)
#include <cuda_runtime.h>

// out[b,c,h,w] = x[b,c,h+dy,w+dx] (zero padded), where (dy,dx) come from the
// abs-argmax of the 3x3 weight (hard softmax -> one-hot kernel -> pure shift).

__device__ int2 g_shift;

__global__ void compute_shift_kernel(const float* __restrict__ w9) {
    // Single thread: argmax of |w| over 9 elements, first occurrence wins
    float best = -1.0f;
    int bi = 0;
    #pragma unroll
    for (int i = 0; i < 9; ++i) {
        float a = fabsf(w9[i]);
        if (a > best) { best = a; bi = i; }
    }
    int ki = bi / 3;   // kernel row
    int kj = bi % 3;   // kernel col
    // cross-correlation with padding 1: src = (h + ki - 1, w + kj - 1)
    g_shift = make_int2(ki - 1, kj - 1);
}

__global__ __launch_bounds__(256) void shift_copy_kernel(
    const float* __restrict__ x, float* __restrict__ out, int total_chunks)
{
    int idx = blockIdx.x * blockDim.x + threadIdx.x;
    if (idx >= total_chunks) return;

    int2 s = g_shift;
    int dy = s.x, dx = s.y;

    // chunk decomposition: W=256 -> 64 float4 chunks per row, H=256 rows
    int wq = idx & 63;          // float4 chunk within row
    int h  = (idx >> 6) & 255;  // row
    int bc = idx >> 14;         // fused batch*channel plane

    float4 v = make_float4(0.f, 0.f, 0.f, 0.f);
    int sh = h + dy;
    if ((unsigned)sh < 256u) {
        const float* row = x + (((size_t)bc << 8) + (size_t)sh) * 256;
        if (dx == 0) {
            v = *reinterpret_cast<const float4*>(row + (wq << 2));
        } else {
            int w0 = (wq << 2) + dx;
            v.x = ((unsigned)(w0 + 0) < 256u) ? __ldg(row + w0 + 0) : 0.f;
            v.y = ((unsigned)(w0 + 1) < 256u) ? __ldg(row + w0 + 1) : 0.f;
            v.z = ((unsigned)(w0 + 2) < 256u) ? __ldg(row + w0 + 2) : 0.f;
            v.w = ((unsigned)(w0 + 3) < 256u) ? __ldg(row + w0 + 3) : 0.f;
        }
    }
    reinterpret_cast<float4*>(out)[idx] = v;
}

extern "C" void kernel_launch(void* const* d_in, const int* in_sizes, int n_in,
                              void* d_out, int out_size) {
    const float* x = (const float*)d_in[0];
    const float* w = (const float*)d_in[1];
    float* out = (float*)d_out;

    compute_shift_kernel<<<1, 1>>>(w);

    int total_chunks = out_size / 4;           // float4 chunks
    int threads = 256;
    int blocks = (total_chunks + threads - 1) / threads;
    shift_copy_kernel<<<blocks, threads>>>(x, out, total_chunks);
}

// round 2
// speedup vs baseline: 1.0722x; 1.0722x over previous
#include <cuda_runtime.h>

// Depthwise 3x3 conv with hard-one-hot kernel == pure spatial shift with zero pad:
//   out[b,c,h,w] = x[b,c, h+dy, w+dx],  (dy,dx) = argmax(|weight|) - 1
//
// One warp per image row (W=256 -> 8 floats/lane = 2 aligned float4).
// Horizontal shift handled by register shuffle; the element that shuffles in
// past lane 0 / lane 31 is exactly the zero-padding value. All loads/stores
// are aligned 128-bit => perfect sector efficiency.

__global__ __launch_bounds__(256) void shift_row_kernel(
    const float* __restrict__ x, const float* __restrict__ w9,
    float* __restrict__ out)
{
    __shared__ int2 s_shift;
    if (threadIdx.x == 0) {
        float best = -1.0f;
        int bi = 0;
        #pragma unroll
        for (int i = 0; i < 9; ++i) {
            float a = fabsf(w9[i]);
            if (a > best) { best = a; bi = i; }   // first occurrence wins (jnp.argmax)
        }
        s_shift = make_int2(bi / 3 - 1, bi % 3 - 1);
    }
    __syncthreads();
    const int dy = s_shift.x;
    const int dx = s_shift.y;

    const int gwarp = (blockIdx.x * blockDim.x + threadIdx.x) >> 5;  // global row id
    const int lane  = threadIdx.x & 31;

    const int h = gwarp & 255;            // row within plane
    const size_t plane = (size_t)(gwarp >> 8);  // fused b*c plane index
    const int sh = h + dy;

    float4 o0, o1;
    if ((unsigned)sh < 256u) {            // uniform per warp
        const float4* src = reinterpret_cast<const float4*>(
            x + ((plane << 8) + (size_t)sh) * 256) + (lane << 1);
        float4 r0 = src[0];
        float4 r1 = src[1];
        if (dx == 0) {
            o0 = r0; o1 = r1;
        } else if (dx > 0) {
            // out col c = src col c+1 ; need src[8l+8] = lane+1's r0.x
            float nxt = __shfl_down_sync(0xffffffffu, r0.x, 1);
            if (lane == 31) nxt = 0.0f;   // col 256 -> zero pad
            o0 = make_float4(r0.y, r0.z, r0.w, r1.x);
            o1 = make_float4(r1.y, r1.z, r1.w, nxt);
        } else {
            // out col c = src col c-1 ; need src[8l-1] = lane-1's r1.w
            float prv = __shfl_up_sync(0xffffffffu, r1.w, 1);
            if (lane == 0) prv = 0.0f;    // col -1 -> zero pad
            o0 = make_float4(prv, r0.x, r0.y, r0.z);
            o1 = make_float4(r0.w, r1.x, r1.y, r1.z);
        }
    } else {
        o0 = make_float4(0.f, 0.f, 0.f, 0.f);
        o1 = o0;
    }

    float4* dst = reinterpret_cast<float4*>(out) + ((size_t)gwarp << 6) + (lane << 1);
    dst[0] = o0;
    dst[1] = o1;
}

extern "C" void kernel_launch(void* const* d_in, const int* in_sizes, int n_in,
                              void* d_out, int out_size) {
    const float* x = (const float*)d_in[0];
    const float* w = (const float*)d_in[1];
    float* out = (float*)d_out;

    // out_size = B*C*H*W = 67,108,864 ; rows = out_size / 256 = 262,144
    int nrows  = out_size >> 8;
    int blocks = nrows >> 3;   // 8 warps (rows) per 256-thread block
    shift_row_kernel<<<blocks, 256>>>(x, w, out);
}